// round 9
// baseline (speedup 1.0000x reference)
#include <cuda_runtime.h>
#include <cstdint>
#include <cstddef>

#define BATCH 256
#define GEN 200
#define HID 200
#define FOUT 200
#define FC_IN 4608
#define NTOT 921600          // FC_IN * FOUT
#define IC 32                // i-values per CTA in big GEMM
#define LDH 204              // padded leading dim for H tile in smem
#define KC 40                // K-chunk per cp.async stage
#define SW_BUF 8000          // KC * 200 floats per buffer

// ---------------- scratch (device globals; no allocation allowed) ----------------
__device__ float g_hcw[BATCH * HID];
__device__ float g_hcb[BATCH * HID];
__device__ float g_hfw[BATCH * HID];
__device__ float g_hfb[BATCH * HID];
__device__ float g_convw[BATCH * 288];
__device__ float g_convb[BATCH * 32];
__device__ float g_fcb[BATCH * FOUT];
__device__ float g_x[BATCH * FC_IN];
__device__ float g_o[BATCH * FOUT];

// ---------------- small helpers ----------------
__device__ __forceinline__ void cp16(float* dst, const float* src) {
    uint32_t s = (uint32_t)__cvta_generic_to_shared(dst);
    asm volatile("cp.async.cg.shared.global [%0], [%1], 16;\n" :: "r"(s), "l"(src));
}
__device__ __forceinline__ uint32_t f2tf(float v) {
    uint32_t r;
    asm("cvt.rna.tf32.f32 %0, %1;" : "=r"(r) : "f"(v));
    return r;
}
__device__ __forceinline__ void mma8(float* c, const uint32_t* a, uint32_t b0, uint32_t b1) {
    asm volatile(
        "mma.sync.aligned.m16n8k8.row.col.f32.tf32.tf32.f32 "
        "{%0,%1,%2,%3}, {%4,%5,%6,%7}, {%8,%9}, {%0,%1,%2,%3};"
        : "+f"(c[0]), "+f"(c[1]), "+f"(c[2]), "+f"(c[3])
        : "r"(a[0]), "r"(a[1]), "r"(a[2]), "r"(a[3]), "r"(b0), "r"(b1));
}

// ---------------- hypernetwork hidden: h = relu(r @ W1 + b1) ----------------
__global__ void gen_hidden(const float* __restrict__ r, const float* __restrict__ W1,
                           const float* __restrict__ b1, float* __restrict__ h) {
    __shared__ float sr[GEN];
    int b = blockIdx.x;
    for (int k = threadIdx.x; k < GEN; k += blockDim.x) sr[k] = r[b * GEN + k];
    __syncthreads();
    int j = threadIdx.x;
    if (j < HID) {
        float acc = b1[j];
#pragma unroll 4
        for (int k = 0; k < GEN; k++) acc = fmaf(sr[k], W1[k * HID + j], acc);
        h[b * HID + j] = fmaxf(acc, 0.f);
    }
}

// ---------------- small generator outputs: out = relu(h @ W2 + b2) ----------------
__global__ void gen_small(const float* __restrict__ h, const float* __restrict__ W2,
                          const float* __restrict__ b2, float* __restrict__ out, int OD) {
    __shared__ float sh[HID];
    int b = blockIdx.x;
    for (int k = threadIdx.x; k < HID; k += blockDim.x) sh[k] = h[b * HID + k];
    __syncthreads();
    int j = blockIdx.y * blockDim.x + threadIdx.x;
    if (j < OD) {
        float acc = b2[j];
#pragma unroll 4
        for (int k = 0; k < HID; k++) acc = fmaf(sh[k], W2[k * OD + j], acc);
        out[b * OD + j] = fmaxf(acc, 0.f);
    }
}

// ---------------- per-sample grouped conv (10x20 img, 32 3x3 filters) + relu ----------------
__global__ void conv_relu(const float* __restrict__ inp) {
    __shared__ float im[200], wf[288], bs[32];
    int b = blockIdx.x;
    for (int k = threadIdx.x; k < 200; k += blockDim.x) im[k] = inp[b * 200 + k];
    for (int k = threadIdx.x; k < 288; k += blockDim.x) wf[k] = g_convw[b * 288 + k];
    if (threadIdx.x < 32) bs[threadIdx.x] = g_convb[b * 32 + threadIdx.x];
    __syncthreads();
    for (int idx = threadIdx.x; idx < 4608; idx += blockDim.x) {
        int c = idx / 144, r2 = idx - c * 144;
        int oh = r2 / 18, ow = r2 - oh * 18;
        const float* w = &wf[c * 9];
        float acc = bs[c];
#pragma unroll
        for (int dy = 0; dy < 3; dy++)
#pragma unroll
            for (int dx = 0; dx < 3; dx++)
                acc = fmaf(im[(oh + dy) * 20 + ow + dx], w[dy * 3 + dx], acc);
        g_x[b * 4608 + idx] = fmaxf(acc, 0.f);
    }
}

__global__ void zero_o() {
    int i = blockIdx.x * blockDim.x + threadIdx.x;
    if (i < BATCH * FOUT) g_o[i] = 0.f;
}

// ---------------- big fused GEMM: o[b,j] += x[b,i]*relu(h@W2 + b2)[b, i*200+j] ----------------
// grid = 2 halves * 144 i-chunks = 288 CTAs; 320 threads = 10 warps (2 M x 5 N)
__global__ __launch_bounds__(320, 1)
void big_gemm(const float* __restrict__ W2, const float* __restrict__ b2) {
    extern __shared__ float smem[];
    float* sH = smem;                         // 128*204
    float* sW = smem + 128 * LDH;             // 2 * 8000
    float* sx = sW + 2 * SW_BUF;              // IC * 128
    float* sb = sx + IC * 128;                // 208

    const int tid = threadIdx.x;
    const int half = blockIdx.x & 1;
    const int chunk = blockIdx.x >> 1;
    const int mb = half * 128;
    const int i0 = chunk * IC;

    // issue stage 0 of the W2 stream immediately (overlap with H/x staging)
    {
        const float* src0 = W2 + (size_t)i0 * 200;  // kc=0, ii=0
        float* dst = sW;
        for (int t = tid; t < 2000; t += 320) {
            int kk = t / 50, nq = t - kk * 50;
            cp16(dst + kk * 200 + nq * 4, src0 + (size_t)kk * NTOT + nq * 4);
        }
        asm volatile("cp.async.commit_group;");
    }

    // stage H (tf32-rounded) and x tiles
    for (int t = tid; t < 128 * 200; t += 320) {
        int r = t / 200, k = t - r * 200;
        sH[r * LDH + k] = __uint_as_float(f2tf(g_hfw[(mb + r) * 200 + k]));
    }
    for (int t = tid; t < 128 * IC; t += 320) {
        int r = t / IC, ii = t - r * IC;
        sx[ii * 128 + r] = g_x[(mb + r) * FC_IN + i0 + ii];
    }

    const int lane = tid & 31, wid = tid >> 5;
    const int gid = lane >> 2, tg = lane & 3;
    const int wm = wid / 5, wn = wid - wm * 5;   // wm:0..1 (M), wn:0..4 (N)

    float C[4][5][4];
    float O[4][5][4];
#pragma unroll
    for (int mt = 0; mt < 4; mt++)
#pragma unroll
        for (int nt = 0; nt < 5; nt++)
#pragma unroll
            for (int q = 0; q < 4; q++) O[mt][nt][q] = 0.f;

    const int S = IC * 5;
    __syncthreads();

#pragma unroll 1
    for (int s = 0; s < S; s++) {
        if (s + 1 < S) {  // prefetch next stage into other buffer
            int ii1 = (s + 1) / 5, kc1 = (s + 1) - ii1 * 5;
            const float* src0 = W2 + (size_t)(kc1 * KC) * NTOT + (size_t)(i0 + ii1) * 200;
            float* dst = sW + ((s + 1) & 1) * SW_BUF;
            for (int t = tid; t < 2000; t += 320) {
                int kk = t / 50, nq = t - kk * 50;
                cp16(dst + kk * 200 + nq * 4, src0 + (size_t)kk * NTOT + nq * 4);
            }
            asm volatile("cp.async.commit_group;");
            asm volatile("cp.async.wait_group 1;");
        } else {
            asm volatile("cp.async.wait_group 0;");
        }
        __syncthreads();

        const int ii = s / 5, kc = s - ii * 5;
        const float* w = sW + (s & 1) * SW_BUF;

        if (kc == 0) {
#pragma unroll
            for (int mt = 0; mt < 4; mt++)
#pragma unroll
                for (int nt = 0; nt < 5; nt++)
#pragma unroll
                    for (int q = 0; q < 4; q++) C[mt][nt][q] = 0.f;
            for (int t = tid; t < 200; t += 320)
                sb[t] = b2[(size_t)(i0 + ii) * 200 + t];
        }

#pragma unroll
        for (int kt = 0; kt < 5; kt++) {
            const int kg = kc * KC + kt * 8;
            uint32_t a[4][4];
#pragma unroll
            for (int mt = 0; mt < 4; mt++) {
                const int R = wm * 64 + mt * 16;
                const float* p0 = &sH[(R + gid) * LDH + kg + tg];
                const float* p1 = &sH[(R + gid + 8) * LDH + kg + tg];
                a[mt][0] = __float_as_uint(p0[0]);
                a[mt][2] = __float_as_uint(p0[4]);
                a[mt][1] = __float_as_uint(p1[0]);
                a[mt][3] = __float_as_uint(p1[4]);
            }
#pragma unroll
            for (int nt = 0; nt < 5; nt++) {
                const int NB = wn * 40 + nt * 8;
                uint32_t b0 = __float_as_uint(w[(kt * 8 + tg) * 200 + NB + gid]);
                uint32_t b1 = __float_as_uint(w[(kt * 8 + tg + 4) * 200 + NB + gid]);
#pragma unroll
                for (int mt = 0; mt < 4; mt++) mma8(C[mt][nt], a[mt], b0, b1);
            }
        }

        if (kc == 4) {  // K complete for this i: bias + relu + x-scale, fold into O
#pragma unroll
            for (int mt = 0; mt < 4; mt++) {
                float x0 = sx[ii * 128 + wm * 64 + mt * 16 + gid];
                float x1 = sx[ii * 128 + wm * 64 + mt * 16 + gid + 8];
#pragma unroll
                for (int nt = 0; nt < 5; nt++) {
                    int col = wn * 40 + nt * 8 + 2 * tg;
                    float bb0 = sb[col], bb1 = sb[col + 1];
                    O[mt][nt][0] = fmaf(x0, fmaxf(C[mt][nt][0] + bb0, 0.f), O[mt][nt][0]);
                    O[mt][nt][1] = fmaf(x0, fmaxf(C[mt][nt][1] + bb1, 0.f), O[mt][nt][1]);
                    O[mt][nt][2] = fmaf(x1, fmaxf(C[mt][nt][2] + bb0, 0.f), O[mt][nt][2]);
                    O[mt][nt][3] = fmaf(x1, fmaxf(C[mt][nt][3] + bb1, 0.f), O[mt][nt][3]);
                }
            }
        }
        __syncthreads();
    }

    // accumulate partials to global
#pragma unroll
    for (int mt = 0; mt < 4; mt++) {
        int r0 = mb + wm * 64 + mt * 16 + gid;
#pragma unroll
        for (int nt = 0; nt < 5; nt++) {
            int col = wn * 40 + nt * 8 + 2 * tg;
            atomicAdd(&g_o[r0 * 200 + col], O[mt][nt][0]);
            atomicAdd(&g_o[r0 * 200 + col + 1], O[mt][nt][1]);
            atomicAdd(&g_o[(r0 + 8) * 200 + col], O[mt][nt][2]);
            atomicAdd(&g_o[(r0 + 8) * 200 + col + 1], O[mt][nt][3]);
        }
    }
}

// ---------------- final: add fc_b, BatchNorm(eval), PReLU ----------------
__global__ void epilogue(const float* __restrict__ gamma, const float* __restrict__ beta,
                         const float* __restrict__ mean, const float* __restrict__ var,
                         const float* __restrict__ alpha, float* __restrict__ out) {
    int idx = blockIdx.x * blockDim.x + threadIdx.x;
    if (idx < BATCH * FOUT) {
        int j = idx % 200;
        float v = g_o[idx] + g_fcb[idx];
        v = (v - mean[j]) * rsqrtf(var[j] + 1e-5f) * gamma[j] + beta[j];
        float a = alpha[0];
        out[idx] = (v >= 0.f) ? v : a * v;
    }
}

// ---------------- launch ----------------
extern "C" void kernel_launch(void* const* d_in, const int* in_sizes, int n_in,
                              void* d_out, int out_size) {
    const float* inp   = (const float*)d_in[0];   // input_embedding (256,200)
    const float* gen   = (const float*)d_in[1];   // generate_embedding (256,200)
    const float* cwW1  = (const float*)d_in[2];
    const float* cwb1  = (const float*)d_in[3];
    const float* cwW2  = (const float*)d_in[4];
    const float* cwb2  = (const float*)d_in[5];
    const float* cbW1  = (const float*)d_in[6];
    const float* cbb1  = (const float*)d_in[7];
    const float* cbW2  = (const float*)d_in[8];
    const float* cbb2  = (const float*)d_in[9];
    const float* fwW1  = (const float*)d_in[10];
    const float* fwb1  = (const float*)d_in[11];
    const float* fwW2  = (const float*)d_in[12];  // (200, 921600)
    const float* fwb2  = (const float*)d_in[13];  // (921600,)
    const float* fbW1  = (const float*)d_in[14];
    const float* fbb1  = (const float*)d_in[15];
    const float* fbW2  = (const float*)d_in[16];
    const float* fbb2  = (const float*)d_in[17];
    const float* bng   = (const float*)d_in[18];
    const float* bnb   = (const float*)d_in[19];
    const float* bnm   = (const float*)d_in[20];
    const float* bnv   = (const float*)d_in[21];
    const float* alpha = (const float*)d_in[22];
    float* out = (float*)d_out;

    const int smem_bytes = (128 * LDH + 2 * SW_BUF + IC * 128 + 208) * (int)sizeof(float);
    cudaFuncSetAttribute(big_gemm, cudaFuncAttributeMaxDynamicSharedMemorySize, smem_bytes);

    // device-global targets resolved inside the kernels
    float *hcw, *hcb, *hfw, *hfb, *convw, *convb, *fcb;
    cudaGetSymbolAddress((void**)&hcw, g_hcw);
    cudaGetSymbolAddress((void**)&hcb, g_hcb);
    cudaGetSymbolAddress((void**)&hfw, g_hfw);
    cudaGetSymbolAddress((void**)&hfb, g_hfb);
    cudaGetSymbolAddress((void**)&convw, g_convw);
    cudaGetSymbolAddress((void**)&convb, g_convb);
    cudaGetSymbolAddress((void**)&fcb, g_fcb);

    gen_hidden<<<BATCH, 256>>>(gen, cwW1, cwb1, hcw);
    gen_hidden<<<BATCH, 256>>>(gen, cbW1, cbb1, hcb);
    gen_hidden<<<BATCH, 256>>>(gen, fwW1, fwb1, hfw);
    gen_hidden<<<BATCH, 256>>>(gen, fbW1, fbb1, hfb);

    gen_small<<<dim3(BATCH, 2), 256>>>(hcw, cwW2, cwb2, convw, 288);
    gen_small<<<dim3(BATCH, 1), 256>>>(hcb, cbW2, cbb2, convb, 32);
    gen_small<<<dim3(BATCH, 1), 256>>>(hfb, fbW2, fbb2, fcb, 200);

    conv_relu<<<BATCH, 256>>>(inp);
    zero_o<<<50, 1024>>>();
    big_gemm<<<288, 320, smem_bytes>>>(fwW2, fwb2);
    epilogue<<<50, 1024>>>(bng, bnb, bnm, bnv, alpha, out);
}

// round 10
// speedup vs baseline: 1.0108x; 1.0108x over previous
#include <cuda_runtime.h>
#include <cstdint>
#include <cstddef>

#define BATCH 256
#define GEN 200
#define HID 200
#define FOUT 200
#define FC_IN 4608
#define NTOT 921600          // FC_IN * FOUT
#define IC 32                // i-values per CTA in big GEMM
#define LDH 204              // padded leading dim for H tile in smem
#define KC 40                // K-chunk per cp.async stage
#define SW_BUF 8000          // KC * 200 floats per buffer

// ---------------- scratch (device globals; no allocation allowed) ----------------
__device__ float g_hcw[BATCH * HID];
__device__ float g_hcb[BATCH * HID];
__device__ float g_hfw[BATCH * HID];
__device__ float g_hfb[BATCH * HID];
__device__ float g_convw[BATCH * 288];
__device__ float g_convb[BATCH * 32];
__device__ float g_fcb[BATCH * FOUT];
__device__ float g_x[BATCH * FC_IN];
__device__ float g_o[BATCH * FOUT];

// ---------------- small helpers ----------------
__device__ __forceinline__ void cp16(float* dst, const float* src) {
    uint32_t s = (uint32_t)__cvta_generic_to_shared(dst);
    asm volatile("cp.async.cg.shared.global [%0], [%1], 16;\n" :: "r"(s), "l"(src));
}
__device__ __forceinline__ uint32_t f2tf(float v) {
    uint32_t r;
    asm("cvt.rna.tf32.f32 %0, %1;" : "=r"(r) : "f"(v));
    return r;
}
__device__ __forceinline__ void mma8(float* c, const uint32_t* a, uint32_t b0, uint32_t b1) {
    asm volatile(
        "mma.sync.aligned.m16n8k8.row.col.f32.tf32.tf32.f32 "
        "{%0,%1,%2,%3}, {%4,%5,%6,%7}, {%8,%9}, {%0,%1,%2,%3};"
        : "+f"(c[0]), "+f"(c[1]), "+f"(c[2]), "+f"(c[3])
        : "r"(a[0]), "r"(a[1]), "r"(a[2]), "r"(a[3]), "r"(b0), "r"(b1));
}

// ---------------- hypernetwork hidden: h = relu(r @ W1 + b1) ----------------
__global__ void gen_hidden(const float* __restrict__ r, const float* __restrict__ W1,
                           const float* __restrict__ b1, float* __restrict__ h) {
    __shared__ float sr[GEN];
    int b = blockIdx.x;
    for (int k = threadIdx.x; k < GEN; k += blockDim.x) sr[k] = r[b * GEN + k];
    __syncthreads();
    int j = threadIdx.x;
    if (j < HID) {
        float acc = b1[j];
#pragma unroll 4
        for (int k = 0; k < GEN; k++) acc = fmaf(sr[k], W1[k * HID + j], acc);
        h[b * HID + j] = fmaxf(acc, 0.f);
    }
}

// ---------------- small generator outputs: out = relu(h @ W2 + b2) ----------------
__global__ void gen_small(const float* __restrict__ h, const float* __restrict__ W2,
                          const float* __restrict__ b2, float* __restrict__ out, int OD) {
    __shared__ float sh[HID];
    int b = blockIdx.x;
    for (int k = threadIdx.x; k < HID; k += blockDim.x) sh[k] = h[b * HID + k];
    __syncthreads();
    int j = blockIdx.y * blockDim.x + threadIdx.x;
    if (j < OD) {
        float acc = b2[j];
#pragma unroll 4
        for (int k = 0; k < HID; k++) acc = fmaf(sh[k], W2[k * OD + j], acc);
        out[b * OD + j] = fmaxf(acc, 0.f);
    }
}

// ---------------- per-sample grouped conv (10x20 img, 32 3x3 filters) + relu ----------------
__global__ void conv_relu(const float* __restrict__ inp) {
    __shared__ float im[200], wf[288], bs[32];
    int b = blockIdx.x;
    for (int k = threadIdx.x; k < 200; k += blockDim.x) im[k] = inp[b * 200 + k];
    for (int k = threadIdx.x; k < 288; k += blockDim.x) wf[k] = g_convw[b * 288 + k];
    if (threadIdx.x < 32) bs[threadIdx.x] = g_convb[b * 32 + threadIdx.x];
    __syncthreads();
    for (int idx = threadIdx.x; idx < 4608; idx += blockDim.x) {
        int c = idx / 144, r2 = idx - c * 144;
        int oh = r2 / 18, ow = r2 - oh * 18;
        const float* w = &wf[c * 9];
        float acc = bs[c];
#pragma unroll
        for (int dy = 0; dy < 3; dy++)
#pragma unroll
            for (int dx = 0; dx < 3; dx++)
                acc = fmaf(im[(oh + dy) * 20 + ow + dx], w[dy * 3 + dx], acc);
        g_x[b * 4608 + idx] = fmaxf(acc, 0.f);
    }
}

__global__ void zero_o() {
    int i = blockIdx.x * blockDim.x + threadIdx.x;
    if (i < BATCH * FOUT) g_o[i] = 0.f;
}

// ---------------- big fused GEMM: o[b,j] += x[b,i]*relu(h@W2 + b2)[b, i*200+j] ----------------
// grid = 2 halves * 144 i-chunks = 288 CTAs; 320 threads = 10 warps (2 M x 5 N)
__global__ __launch_bounds__(320, 1)
void big_gemm(const float* __restrict__ W2, const float* __restrict__ b2) {
    extern __shared__ float smem[];
    float* sH = smem;                         // 128*204
    float* sW = smem + 128 * LDH;             // 2 * 8000
    float* sx = sW + 2 * SW_BUF;              // IC * 128
    float* sb = sx + IC * 128;                // 208

    const int tid = threadIdx.x;
    const int half = blockIdx.x & 1;
    const int chunk = blockIdx.x >> 1;
    const int mb = half * 128;
    const int i0 = chunk * IC;

    // issue stage 0 of the W2 stream immediately (overlap with H/x staging)
    {
        const float* src0 = W2 + (size_t)i0 * 200;  // kc=0, ii=0
        float* dst = sW;
        for (int t = tid; t < 2000; t += 320) {
            int kk = t / 50, nq = t - kk * 50;
            cp16(dst + kk * 200 + nq * 4, src0 + (size_t)kk * NTOT + nq * 4);
        }
        asm volatile("cp.async.commit_group;");
    }

    // stage H (tf32-rounded) and x tiles
    for (int t = tid; t < 128 * 200; t += 320) {
        int r = t / 200, k = t - r * 200;
        sH[r * LDH + k] = __uint_as_float(f2tf(g_hfw[(mb + r) * 200 + k]));
    }
    for (int t = tid; t < 128 * IC; t += 320) {
        int r = t / IC, ii = t - r * IC;
        sx[ii * 128 + r] = g_x[(mb + r) * FC_IN + i0 + ii];
    }

    const int lane = tid & 31, wid = tid >> 5;
    const int gid = lane >> 2, tg = lane & 3;
    const int wm = wid / 5, wn = wid - wm * 5;   // wm:0..1 (M), wn:0..4 (N)

    float C[4][5][4];
    float O[4][5][4];
#pragma unroll
    for (int mt = 0; mt < 4; mt++)
#pragma unroll
        for (int nt = 0; nt < 5; nt++)
#pragma unroll
            for (int q = 0; q < 4; q++) O[mt][nt][q] = 0.f;

    const int S = IC * 5;
    __syncthreads();

#pragma unroll 1
    for (int s = 0; s < S; s++) {
        if (s + 1 < S) {  // prefetch next stage into other buffer
            int ii1 = (s + 1) / 5, kc1 = (s + 1) - ii1 * 5;
            const float* src0 = W2 + (size_t)(kc1 * KC) * NTOT + (size_t)(i0 + ii1) * 200;
            float* dst = sW + ((s + 1) & 1) * SW_BUF;
            for (int t = tid; t < 2000; t += 320) {
                int kk = t / 50, nq = t - kk * 50;
                cp16(dst + kk * 200 + nq * 4, src0 + (size_t)kk * NTOT + nq * 4);
            }
            asm volatile("cp.async.commit_group;");
            asm volatile("cp.async.wait_group 1;");
        } else {
            asm volatile("cp.async.wait_group 0;");
        }
        __syncthreads();

        const int ii = s / 5, kc = s - ii * 5;
        const float* w = sW + (s & 1) * SW_BUF;

        if (kc == 0) {
#pragma unroll
            for (int mt = 0; mt < 4; mt++)
#pragma unroll
                for (int nt = 0; nt < 5; nt++)
#pragma unroll
                    for (int q = 0; q < 4; q++) C[mt][nt][q] = 0.f;
            for (int t = tid; t < 200; t += 320)
                sb[t] = b2[(size_t)(i0 + ii) * 200 + t];
        }

#pragma unroll
        for (int kt = 0; kt < 5; kt++) {
            const int kg = kc * KC + kt * 8;
            uint32_t a[4][4];
#pragma unroll
            for (int mt = 0; mt < 4; mt++) {
                const int R = wm * 64 + mt * 16;
                const float* p0 = &sH[(R + gid) * LDH + kg + tg];
                const float* p1 = &sH[(R + gid + 8) * LDH + kg + tg];
                a[mt][0] = __float_as_uint(p0[0]);
                a[mt][2] = __float_as_uint(p0[4]);
                a[mt][1] = __float_as_uint(p1[0]);
                a[mt][3] = __float_as_uint(p1[4]);
            }
#pragma unroll
            for (int nt = 0; nt < 5; nt++) {
                const int NB = wn * 40 + nt * 8;
                uint32_t b0 = __float_as_uint(w[(kt * 8 + tg) * 200 + NB + gid]);
                uint32_t b1 = __float_as_uint(w[(kt * 8 + tg + 4) * 200 + NB + gid]);
#pragma unroll
                for (int mt = 0; mt < 4; mt++) mma8(C[mt][nt], a[mt], b0, b1);
            }
        }

        if (kc == 4) {  // K complete for this i: bias + relu + x-scale, fold into O
#pragma unroll
            for (int mt = 0; mt < 4; mt++) {
                float x0 = sx[ii * 128 + wm * 64 + mt * 16 + gid];
                float x1 = sx[ii * 128 + wm * 64 + mt * 16 + gid + 8];
#pragma unroll
                for (int nt = 0; nt < 5; nt++) {
                    int col = wn * 40 + nt * 8 + 2 * tg;
                    float bb0 = sb[col], bb1 = sb[col + 1];
                    O[mt][nt][0] = fmaf(x0, fmaxf(C[mt][nt][0] + bb0, 0.f), O[mt][nt][0]);
                    O[mt][nt][1] = fmaf(x0, fmaxf(C[mt][nt][1] + bb1, 0.f), O[mt][nt][1]);
                    O[mt][nt][2] = fmaf(x1, fmaxf(C[mt][nt][2] + bb0, 0.f), O[mt][nt][2]);
                    O[mt][nt][3] = fmaf(x1, fmaxf(C[mt][nt][3] + bb1, 0.f), O[mt][nt][3]);
                }
            }
        }
        __syncthreads();
    }

    // accumulate partials to global
#pragma unroll
    for (int mt = 0; mt < 4; mt++) {
        int r0 = mb + wm * 64 + mt * 16 + gid;
#pragma unroll
        for (int nt = 0; nt < 5; nt++) {
            int col = wn * 40 + nt * 8 + 2 * tg;
            atomicAdd(&g_o[r0 * 200 + col], O[mt][nt][0]);
            atomicAdd(&g_o[r0 * 200 + col + 1], O[mt][nt][1]);
            atomicAdd(&g_o[(r0 + 8) * 200 + col], O[mt][nt][2]);
            atomicAdd(&g_o[(r0 + 8) * 200 + col + 1], O[mt][nt][3]);
        }
    }
}

// ---------------- final: add fc_b, BatchNorm(eval), PReLU ----------------
__global__ void epilogue(const float* __restrict__ gamma, const float* __restrict__ beta,
                         const float* __restrict__ mean, const float* __restrict__ var,
                         const float* __restrict__ alpha, float* __restrict__ out) {
    int idx = blockIdx.x * blockDim.x + threadIdx.x;
    if (idx < BATCH * FOUT) {
        int j = idx % 200;
        float v = g_o[idx] + g_fcb[idx];
        v = (v - mean[j]) * rsqrtf(var[j] + 1e-5f) * gamma[j] + beta[j];
        float a = alpha[0];
        out[idx] = (v >= 0.f) ? v : a * v;
    }
}

// ---------------- launch ----------------
extern "C" void kernel_launch(void* const* d_in, const int* in_sizes, int n_in,
                              void* d_out, int out_size) {
    const float* inp   = (const float*)d_in[0];   // input_embedding (256,200)
    const float* gen   = (const float*)d_in[1];   // generate_embedding (256,200)
    const float* cwW1  = (const float*)d_in[2];
    const float* cwb1  = (const float*)d_in[3];
    const float* cwW2  = (const float*)d_in[4];
    const float* cwb2  = (const float*)d_in[5];
    const float* cbW1  = (const float*)d_in[6];
    const float* cbb1  = (const float*)d_in[7];
    const float* cbW2  = (const float*)d_in[8];
    const float* cbb2  = (const float*)d_in[9];
    const float* fwW1  = (const float*)d_in[10];
    const float* fwb1  = (const float*)d_in[11];
    const float* fwW2  = (const float*)d_in[12];  // (200, 921600)
    const float* fwb2  = (const float*)d_in[13];  // (921600,)
    const float* fbW1  = (const float*)d_in[14];
    const float* fbb1  = (const float*)d_in[15];
    const float* fbW2  = (const float*)d_in[16];
    const float* fbb2  = (const float*)d_in[17];
    const float* bng   = (const float*)d_in[18];
    const float* bnb   = (const float*)d_in[19];
    const float* bnm   = (const float*)d_in[20];
    const float* bnv   = (const float*)d_in[21];
    const float* alpha = (const float*)d_in[22];
    float* out = (float*)d_out;

    const int smem_bytes = (128 * LDH + 2 * SW_BUF + IC * 128 + 208) * (int)sizeof(float);
    cudaFuncSetAttribute(big_gemm, cudaFuncAttributeMaxDynamicSharedMemorySize, smem_bytes);

    // device-global targets resolved inside the kernels
    float *hcw, *hcb, *hfw, *hfb, *convw, *convb, *fcb;
    cudaGetSymbolAddress((void**)&hcw, g_hcw);
    cudaGetSymbolAddress((void**)&hcb, g_hcb);
    cudaGetSymbolAddress((void**)&hfw, g_hfw);
    cudaGetSymbolAddress((void**)&hfb, g_hfb);
    cudaGetSymbolAddress((void**)&convw, g_convw);
    cudaGetSymbolAddress((void**)&convb, g_convb);
    cudaGetSymbolAddress((void**)&fcb, g_fcb);

    gen_hidden<<<BATCH, 256>>>(gen, cwW1, cwb1, hcw);
    gen_hidden<<<BATCH, 256>>>(gen, cbW1, cbb1, hcb);
    gen_hidden<<<BATCH, 256>>>(gen, fwW1, fwb1, hfw);
    gen_hidden<<<BATCH, 256>>>(gen, fbW1, fbb1, hfb);

    gen_small<<<dim3(BATCH, 2), 256>>>(hcw, cwW2, cwb2, convw, 288);
    gen_small<<<dim3(BATCH, 1), 256>>>(hcb, cbW2, cbb2, convb, 32);
    gen_small<<<dim3(BATCH, 1), 256>>>(hfb, fbW2, fbb2, fcb, 200);

    conv_relu<<<BATCH, 256>>>(inp);
    zero_o<<<50, 1024>>>();
    big_gemm<<<288, 320, smem_bytes>>>(fwW2, fwb2);
    epilogue<<<50, 1024>>>(bng, bnb, bnm, bnv, alpha, out);
}